// round 1
// baseline (speedup 1.0000x reference)
#include <cuda_runtime.h>
#include <math.h>

// ---------------- problem constants ----------------
#define E_N      200000
#define A_NUM    8000
#define T_N      1000000
#define R_N      128
#define NCAT     672          // 16 + 16 + 16 + 112 + 512
#define EMB_EDGE 512

// output layout (floats) in d_out: m, atom_update, output, rad_e2e, cir_e2e
#define OFF_M    0ull
#define OFF_AT   102400000ull
#define OFF_OUT  105600000ull
#define OFF_RE2E 108800000ull
#define OFF_CIR  112000000ull

// ---------------- device scratch (no allocs allowed) ----------------
__device__ float g_radW1[(size_t)E_N * 112];          // rad @ W_cbf_tint  (E,7,16)
__device__ float g_hW[2ull * A_NUM * EMB_EDGE];       // h@W_edge[0:256] ; h@W_edge[256:512]
__device__ float g_Wcat[R_N * NCAT];                  // concatenated 128x672 weight

// ---------------- f32x2 packed math helpers ----------------
__device__ __forceinline__ void ffma2(unsigned long long& d, unsigned long long a,
                                      unsigned long long b) {
    asm("fma.rn.f32x2 %0, %1, %2, %3;" : "=l"(d) : "l"(a), "l"(b), "l"(d));
}
__device__ __forceinline__ unsigned long long pack2(float x, float y) {
    unsigned long long r;
    asm("mov.b64 %0, {%1, %2};" : "=l"(r) : "f"(x), "f"(y));
    return r;
}
union F4U { float4 f; unsigned long long u[2]; };

// ---------------- kernel 1: build concatenated weight ----------------
__global__ void build_wcat(const float* __restrict__ Wt, const float* __restrict__ Wc,
                           const float* __restrict__ Wh, const float* __restrict__ Wo,
                           const float* __restrict__ We) {
    int i = blockIdx.x * blockDim.x + threadIdx.x;
    if (i >= R_N * NCAT) return;
    int r = i / NCAT, n = i - r * NCAT;
    float v;
    if (n < 16)        v = Wt[r * 16 + n];                 // rad_e2e
    else if (n < 32)   v = Wh[r * 16 + (n - 16)];          // atom_update
    else if (n < 48)   v = Wo[r * 16 + (n - 32)];          // output
    else if (n < 160)  v = Wc[r * 112 + (n - 48)];         // radW1 (cbf tint)
    else               v = We[(size_t)(512 + r) * EMB_EDGE + (n - 160)]; // m (rad part)
    g_Wcat[i] = v;
}

// ---------------- kernel 2: hW = h @ W_edge[z*256:(z+1)*256]  z=0,1 ----------------
__global__ void __launch_bounds__(256, 2)
gemm_hw(const float* __restrict__ h, const float* __restrict__ We) {
    __shared__ float As[32][132];
    __shared__ float Bs[32][132];
    const int z = blockIdx.z;
    const float* B = We + (size_t)z * 256 * EMB_EDGE;
    float* C = g_hW + (size_t)z * A_NUM * EMB_EDGE;
    const int m0 = blockIdx.y * 128;
    const int n0 = blockIdx.x * 128;
    const int tid = threadIdx.x;
    const int tx = tid & 15, ty = tid >> 4;

    unsigned long long acc[8][4];
#pragma unroll
    for (int i = 0; i < 8; ++i)
#pragma unroll
        for (int j = 0; j < 4; ++j) acc[i][j] = 0ull;

    for (int k0 = 0; k0 < 256; k0 += 32) {
        if (k0) __syncthreads();
#pragma unroll
        for (int i = tid; i < 128 * 32; i += 256) {
            int m = i >> 5, kk = i & 31;
            As[kk][m] = (m0 + m < A_NUM) ? h[(size_t)(m0 + m) * 256 + k0 + kk] : 0.f;
        }
#pragma unroll
        for (int i = tid * 4; i < 32 * 128; i += 1024) {
            int kk = i >> 7, n = i & 127;
            *(float4*)&Bs[kk][n] = *(const float4*)&B[(size_t)(k0 + kk) * EMB_EDGE + n0 + n];
        }
        __syncthreads();
#pragma unroll
        for (int kk = 0; kk < 32; ++kk) {
            float4 a0 = *(const float4*)&As[kk][ty * 8];
            float4 a1 = *(const float4*)&As[kk][ty * 8 + 4];
            F4U b0, b1;
            b0.f = *(const float4*)&Bs[kk][tx * 8];
            b1.f = *(const float4*)&Bs[kk][tx * 8 + 4];
            unsigned long long bb[4] = {b0.u[0], b0.u[1], b1.u[0], b1.u[1]};
            float av[8] = {a0.x, a0.y, a0.z, a0.w, a1.x, a1.y, a1.z, a1.w};
#pragma unroll
            for (int i = 0; i < 8; ++i) {
                unsigned long long a2 = pack2(av[i], av[i]);
#pragma unroll
                for (int j = 0; j < 4; ++j) ffma2(acc[i][j], a2, bb[j]);
            }
        }
    }
#pragma unroll
    for (int i = 0; i < 8; ++i) {
        int m = m0 + ty * 8 + i;
        if (m >= A_NUM) continue;
        float v[8];
#pragma unroll
        for (int j = 0; j < 4; ++j) {
            v[2 * j]     = __uint_as_float((unsigned)(acc[i][j] & 0xffffffffull));
            v[2 * j + 1] = __uint_as_float((unsigned)(acc[i][j] >> 32));
        }
        float* dst = C + (size_t)m * EMB_EDGE + n0 + tx * 8;
        *(float4*)dst       = make_float4(v[0], v[1], v[2], v[3]);
        *(float4*)(dst + 4) = make_float4(v[4], v[5], v[6], v[7]);
    }
}

// ---------------- kernel 3: fused  rad(on-the-fly) @ Wcat + epilogues ----------------
__global__ void __launch_bounds__(256)
main_fused(const float* __restrict__ dist, const int* __restrict__ eis,
           const int* __restrict__ eit, float* __restrict__ out) {
    extern __shared__ float smem[];
    float(*As)[132] = (float(*)[132])smem;                 // [128][132]   rad^T tile
    float(*Bs)[132] = (float(*)[132])(smem + 128 * 132);   // [32][132]

    const int tid = threadIdx.x;
    const int e0 = blockIdx.y * 128;
    const int n0 = blockIdx.x * 128;

    // ---- fill A panel: rad[e][r] = env(e) * exp(-0.5*(u-r)^2),  u = 127*d/12 ----
    {
        const int el = tid & 127;
        const int dir = tid >> 7;
        const int e = e0 + el;
        float u = 0.f, f = 0.f, vc = 0.f;
        int r0 = 0;
        if (e < E_N) {
            float ds = dist[e] * (1.0f / 12.0f);
            float ds2 = ds * ds;
            float ds5 = ds2 * ds2 * ds;
            float env = (ds < 1.f) ? (1.f + ds5 * (-21.f + ds * (35.f - 15.f * ds))) : 0.f;
            u = ds * 127.f;
            r0 = __float2int_rn(u);
            r0 = max(0, min(127, r0));
            f = u - (float)r0;
            vc = env * expf(-0.5f * f * f);
        }
        const float E1 = 0.36787944117144233f;  // exp(-1)
        if (dir == 0) {
            As[r0][el] = vc;
            float ratio = __expf(-f - 0.5f);
            float v = vc;
            for (int r = r0 - 1; r >= 0; --r) { v *= ratio; ratio *= E1; As[r][el] = v; }
        } else {
            float ratio = __expf(f - 0.5f);
            float v = vc;
            for (int r = r0 + 1; r < 128; ++r) { v *= ratio; ratio *= E1; As[r][el] = v; }
        }
    }
    __syncthreads();

    const int tx = tid & 15, ty = tid >> 4;
    unsigned long long acc[8][4];
#pragma unroll
    for (int i = 0; i < 8; ++i)
#pragma unroll
        for (int j = 0; j < 4; ++j) acc[i][j] = 0ull;

    for (int kt = 0; kt < 4; ++kt) {
        if (kt) __syncthreads();
#pragma unroll
        for (int i = tid * 4; i < 32 * 128; i += 1024) {
            int kk = i >> 7, n = i & 127;
            float4 v = make_float4(0.f, 0.f, 0.f, 0.f);
            int gn = n0 + n;
            if (gn < NCAT) v = *(const float4*)&g_Wcat[(size_t)(kt * 32 + kk) * NCAT + gn];
            *(float4*)&Bs[kk][n] = v;
        }
        __syncthreads();
#pragma unroll
        for (int kk = 0; kk < 32; ++kk) {
            const int k = kt * 32 + kk;
            float4 a0 = *(const float4*)&As[k][ty * 8];
            float4 a1 = *(const float4*)&As[k][ty * 8 + 4];
            F4U b0, b1;
            b0.f = *(const float4*)&Bs[kk][tx * 8];
            b1.f = *(const float4*)&Bs[kk][tx * 8 + 4];
            unsigned long long bb[4] = {b0.u[0], b0.u[1], b1.u[0], b1.u[1]};
            float av[8] = {a0.x, a0.y, a0.z, a0.w, a1.x, a1.y, a1.z, a1.w};
#pragma unroll
            for (int i = 0; i < 8; ++i) {
                unsigned long long a2 = pack2(av[i], av[i]);
#pragma unroll
                for (int j = 0; j < 4; ++j) ffma2(acc[i][j], a2, bb[j]);
            }
        }
    }

    // ---- epilogue: route column groups ----
    const int nb = n0 + tx * 8;            // 8-wide group never straddles a region boundary
    if (nb >= NCAT) return;
#pragma unroll
    for (int i = 0; i < 8; ++i) {
        int e = e0 + ty * 8 + i;
        if (e >= E_N) continue;
        float v[8];
#pragma unroll
        for (int j = 0; j < 4; ++j) {
            v[2 * j]     = __uint_as_float((unsigned)(acc[i][j] & 0xffffffffull));
            v[2 * j + 1] = __uint_as_float((unsigned)(acc[i][j] >> 32));
        }
        if (nb >= 160) {
            // m = scaled_silu(acc + hW1[s] + hW2[t])
            int j2 = nb - 160;
            int si = eis[e], ti = eit[e];
            const float* hw1 = g_hW + (size_t)si * EMB_EDGE + j2;
            const float* hw2 = g_hW + (size_t)A_NUM * EMB_EDGE + (size_t)ti * EMB_EDGE + j2;
            float4 p1a = *(const float4*)hw1, p1b = *(const float4*)(hw1 + 4);
            float4 p2a = *(const float4*)hw2, p2b = *(const float4*)(hw2 + 4);
            float add[8] = {p1a.x + p2a.x, p1a.y + p2a.y, p1a.z + p2a.z, p1a.w + p2a.w,
                            p1b.x + p2b.x, p1b.y + p2b.y, p1b.z + p2b.z, p1b.w + p2b.w};
            float r[8];
#pragma unroll
            for (int j = 0; j < 8; ++j) {
                float x = v[j] + add[j];
                r[j] = x * (1.0f / 0.6f) / (1.0f + __expf(-x));
            }
            float* dst = out + OFF_M + (size_t)e * EMB_EDGE + j2;
            *(float4*)dst       = make_float4(r[0], r[1], r[2], r[3]);
            *(float4*)(dst + 4) = make_float4(r[4], r[5], r[6], r[7]);
        } else if (nb >= 48) {
            float* dst = g_radW1 + (size_t)e * 112 + (nb - 48);
            *(float4*)dst       = make_float4(v[0], v[1], v[2], v[3]);
            *(float4*)(dst + 4) = make_float4(v[4], v[5], v[6], v[7]);
        } else {
            int seg = nb >> 4;  // 0: rad_e2e, 1: atom_update, 2: output
            size_t base = (seg == 0) ? OFF_RE2E : (seg == 1) ? OFF_AT : OFF_OUT;
            float* dst = out + base + (size_t)e * 16 + (nb & 15);
            *(float4*)dst       = make_float4(v[0], v[1], v[2], v[3]);
            *(float4*)(dst + 4) = make_float4(v[4], v[5], v[6], v[7]);
        }
    }
}

// ---------------- kernel 4: triplets (cir_e2e) ----------------
__global__ void __launch_bounds__(256)
trip_kernel(const int* __restrict__ tin, const int* __restrict__ tout,
            const float* __restrict__ vec, float* __restrict__ out) {
    int g = blockIdx.x * blockDim.x + threadIdx.x;
    int t = g >> 4;
    int c = g & 15;
    if (t >= T_N) return;
    int lane = threadIdx.x & 31;

    int i_out = 0;
    float cosv = 0.f;
    if ((lane & 15) == 0) {
        int i_in = tin[t];
        i_out = tout[t];
        float ax = vec[3 * (size_t)i_out + 0], ay = vec[3 * (size_t)i_out + 1],
              az = vec[3 * (size_t)i_out + 2];
        float bx = vec[3 * (size_t)i_in + 0], by = vec[3 * (size_t)i_in + 1],
              bz = vec[3 * (size_t)i_in + 2];
        cosv = ax * bx + ay * by + az * bz;
        cosv = fminf(1.f, fmaxf(-1.f, cosv));
    }
    const unsigned mask = 0xffffffffu;
    i_out = __shfl_sync(mask, i_out, lane & 16, 32);
    cosv  = __shfl_sync(mask, cosv, lane & 16, 32);

    const float* row = g_radW1 + (size_t)i_out * 112 + c;
    float x = cosv;
    // Legendre P_l with spherical-harmonic prefactors sqrt((2l+1)/4pi)
    float P0 = 1.f, P1 = x;
    float P2 = (3.f * x * P1 - 1.f * P0) * (1.f / 2.f);
    float P3 = (5.f * x * P2 - 2.f * P1) * (1.f / 3.f);
    float P4 = (7.f * x * P3 - 3.f * P2) * (1.f / 4.f);
    float P5 = (9.f * x * P4 - 4.f * P3) * (1.f / 5.f);
    float P6 = (11.f * x * P5 - 5.f * P4) * (1.f / 6.f);

    float acc;
    acc  = 0.28209479177387814f * P0 * row[0];
    acc += 0.4886025119029199f  * P1 * row[16];
    acc += 0.6307831305050401f  * P2 * row[32];
    acc += 0.7463526651802308f  * P3 * row[48];
    acc += 0.8462843753216345f  * P4 * row[64];
    acc += 0.9356025796273889f  * P5 * row[80];
    acc += 1.0171072362820548f  * P6 * row[96];

    out[OFF_CIR + (size_t)t * 16 + c] = acc;
}

// ---------------- launch ----------------
extern "C" void kernel_launch(void* const* d_in, const int* in_sizes, int n_in,
                              void* d_out, int out_size) {
    const float* h    = (const float*)d_in[0];
    const float* dist = (const float*)d_in[1];
    const float* vec  = (const float*)d_in[2];
    const int*   eis  = (const int*)d_in[3];
    const int*   eit  = (const int*)d_in[4];
    const int*   tin  = (const int*)d_in[5];
    const int*   tout = (const int*)d_in[6];
    const float* Wt   = (const float*)d_in[7];   // W_rbf_tint (128,16)
    const float* Wc   = (const float*)d_in[8];   // W_cbf_tint (128,112)
    const float* Wh   = (const float*)d_in[9];   // W_rbf_h    (128,16)
    const float* Wo   = (const float*)d_in[10];  // W_rbf_out  (128,16)
    const float* We   = (const float*)d_in[11];  // W_edge     (640,512)
    float* out = (float*)d_out;

    // allow 84.5 KB dynamic smem for the fused GEMM (called every launch; idempotent)
    const int MAIN_SMEM = (128 * 132 + 32 * 132) * 4;
    cudaFuncSetAttribute(main_fused, cudaFuncAttributeMaxDynamicSharedMemorySize, MAIN_SMEM);

    build_wcat<<<(R_N * NCAT + 255) / 256, 256>>>(Wt, Wc, Wh, Wo, We);

    gemm_hw<<<dim3(4, (A_NUM + 127) / 128, 2), 256>>>(h, We);

    main_fused<<<dim3((NCAT + 127) / 128, (E_N + 127) / 128), 256, MAIN_SMEM>>>(
        dist, eis, eit, out);

    trip_kernel<<<(T_N * 16) / 256, 256>>>(tin, tout, vec, out);
}